// round 1
// baseline (speedup 1.0000x reference)
#include <cuda_runtime.h>
#include <cuda_bf16.h>

// Problem constants (fixed shapes from reference)
#define BV 4
#define NV 1
#define DV 48
#define HV 32
#define WV 88
#define CV 64
#define NXV 200
#define NYV 200
#define NZV 1
#define NPRIME (BV * NV * DV * HV * WV)   // 540672
#define OUT_ELEMS (BV * NZV * CV * NXV * NYV)  // 10,240,000

__global__ void bev_zero_kernel(float4* __restrict__ out, int n4) {
    int i = blockIdx.x * blockDim.x + threadIdx.x;
    if (i < n4) out[i] = make_float4(0.f, 0.f, 0.f, 0.f);
}

__global__ void bev_scatter_kernel(const float* __restrict__ x,
                                   const float* __restrict__ geom,
                                   const float* __restrict__ mask,
                                   const float* __restrict__ dx,
                                   const float* __restrict__ bx,
                                   float* __restrict__ out) {
    const int lane   = threadIdx.x & 31;
    const int warp   = (blockIdx.x * blockDim.x + threadIdx.x) >> 5;
    const int nwarps = (gridDim.x * blockDim.x) >> 5;

    // dx/bx are tiny; every lane loads them (L1/L2 broadcast, negligible)
    const float dx0 = dx[0], dx1 = dx[1], dx2 = dx[2];
    const float b0 = bx[0] - 0.5f * dx0;
    const float b1 = bx[1] - 0.5f * dx1;
    const float b2 = bx[2] - 0.5f * dx2;

    for (int p = warp; p < NPRIME; p += nwarps) {
        int base = -1;
        if (lane == 0) {
            // geometry -> voxel index (truncation toward zero, matches astype(int32))
            const float gxf = (geom[p * 3 + 0] - b0) / dx0;
            const float gyf = (geom[p * 3 + 1] - b1) / dx1;
            const float gzf = (geom[p * 3 + 2] - b2) / dx2;
            const int ix = (int)gxf;
            const int iy = (int)gyf;
            const int iz = (int)gzf;

            // point decomposition: p = ((b*N + n)*D + d)*H*W + h*W + w
            const int hw = p % (HV * WV);
            const int h  = hw / WV;
            const int w  = hw - h * WV;
            const int bn = p / (DV * HV * WV);   // == b*N + n (N=1)

            const bool kept =
                (ix >= 0) & (ix < NXV) &
                (iy >= 0) & (iy < NYV) &
                (iz >= 0) & (iz < NZV) &
                (mask[(bn * 2 + 1) * (HV * WV) + h * WV + w] > 0.5f);

            if (kept) {
                // out[((b*C + c)*NX + ix)*NY + iy]; channel stride = NX*NY
                base = (bn * CV) * (NXV * NYV) + ix * NYV + iy;
            }
        }
        base = __shfl_sync(0xffffffffu, base, 0);
        if (base >= 0) {
            // lane handles channels 2*lane, 2*lane+1 -> one coalesced float2 load
            const float2 v = *reinterpret_cast<const float2*>(
                x + (long long)p * CV + 2 * lane);
            float* o = out + base + (2 * lane) * (NXV * NYV);
            atomicAdd(o, v.x);
            atomicAdd(o + (NXV * NYV), v.y);
        }
    }
}

extern "C" void kernel_launch(void* const* d_in, const int* in_sizes, int n_in,
                              void* d_out, int out_size) {
    const float* x    = (const float*)d_in[0];
    const float* geom = (const float*)d_in[1];
    const float* mask = (const float*)d_in[2];
    const float* dx   = (const float*)d_in[3];
    const float* bx   = (const float*)d_in[4];
    float* out = (float*)d_out;

    // 1) zero the output (poisoned to 0xAA by harness)
    const int n4 = out_size / 4;
    bev_zero_kernel<<<(n4 + 255) / 256, 256>>>((float4*)out, n4);

    // 2) masked scatter-add; one full wave of persistent warps
    const int blocks = 148 * 8;   // 256 thr/blk -> 2048 thr/SM, one wave
    bev_scatter_kernel<<<blocks, 256>>>(x, geom, mask, dx, bx, out);
}

// round 2
// speedup vs baseline: 1.2617x; 1.2617x over previous
#include <cuda_runtime.h>
#include <cuda_bf16.h>

// Fixed problem shapes
#define BV 4
#define DV 48
#define HV 32
#define WV 88
#define CV 64
#define NXV 200
#define NYV 200
#define HWV (HV * WV)
#define NPRIME (BV * DV * HV * WV)       // 540672 frustum points
#define NXY (NXV * NYV)                  // 40000
#define NGROUP (CV / 4)                  // 16 four-channel groups
#define NGTOT (BV * NGROUP * NXY)        // 2,560,000 groups
#define SCRATCH_ELEMS (NGTOT * 4)        // 10,240,000 floats = 41 MB

// Channel-interleaved accumulator: [b][c4][nxy][4] -> 16B-contiguous groups
// so a point's contribution to 4 channels is one red.global.add.v4.f32.
__device__ float g_scratch[SCRATCH_ELEMS];

__global__ void zero_scratch_kernel(int n4) {
    int i = blockIdx.x * blockDim.x + threadIdx.x;
    float4* p = reinterpret_cast<float4*>(g_scratch);
    if (i < n4) p[i] = make_float4(0.f, 0.f, 0.f, 0.f);
}

__global__ void bev_scatter_kernel(const float* __restrict__ x,
                                   const float* __restrict__ geom,
                                   const float* __restrict__ mask,
                                   const float* __restrict__ dxp,
                                   const float* __restrict__ bxp) {
    const int tid  = blockIdx.x * blockDim.x + threadIdx.x;
    const int sl   = tid & 15;                       // sub-lane in 16-lane group
    const int gid0 = tid >> 4;                       // half-warp id
    const int ngrp = (gridDim.x * blockDim.x) >> 4;

    const float dx0 = dxp[0], dx1 = dxp[1], dx2 = dxp[2];
    const float b0 = bxp[0] - 0.5f * dx0;
    const float b1 = bxp[1] - 0.5f * dx1;
    const float b2 = bxp[2] - 0.5f * dx2;

    for (int p = gid0; p < NPRIME; p += ngrp) {
        int base = -1;
        if (sl == 0) {
            // voxel index; IEEE fp32 div + truncation-toward-zero matches reference
            const float gx = (geom[p * 3 + 0] - b0) / dx0;
            const float gy = (geom[p * 3 + 1] - b1) / dx1;
            const float gz = (geom[p * 3 + 2] - b2) / dx2;
            const int ix = (int)gx;
            const int iy = (int)gy;
            const int iz = (int)gz;

            const int hw = p % HWV;
            const int bn = p / (DV * HWV);           // batch (N=1)

            const bool kept =
                (ix >= 0) & (ix < NXV) &
                (iy >= 0) & (iy < NYV) &
                (iz >= 0) & (iz < 1) &
                (mask[(bn * 2 + 1) * HWV + hw] > 0.5f);

            if (kept) base = bn * (NGROUP * NXY) + ix * NYV + iy;
        }
        base = __shfl_sync(0xffffffffu, base, 0, 16);
        if (base >= 0) {
            // one 16B coalesced load per sub-lane: 256B per point total
            const float4 v = *reinterpret_cast<const float4*>(
                x + (size_t)p * CV + sl * 4);
            float* dst = g_scratch + (size_t)(base + sl * NXY) * 4;
            asm volatile(
                "red.global.add.v4.f32 [%0], {%1, %2, %3, %4};"
                :: "l"(dst), "f"(v.x), "f"(v.y), "f"(v.z), "f"(v.w)
                : "memory");
        }
    }
}

// Interleaved scratch -> planar output. Writes EVERY output element, so no
// separate output zero-init is needed.
__global__ void bev_unpack_kernel(float* __restrict__ out) {
    const int g = blockIdx.x * blockDim.x + threadIdx.x;
    if (g >= NGTOT) return;
    const int nxy = g % NXY;
    const int t   = g / NXY;
    const int c4  = t % NGROUP;
    const int b   = t / NGROUP;

    const float4 v = *reinterpret_cast<const float4*>(g_scratch + (size_t)g * 4);
    float* o = out + (size_t)(b * CV + c4 * 4) * NXY + nxy;
    o[0 * NXY] = v.x;
    o[1 * NXY] = v.y;
    o[2 * NXY] = v.z;
    o[3 * NXY] = v.w;
}

extern "C" void kernel_launch(void* const* d_in, const int* in_sizes, int n_in,
                              void* d_out, int out_size) {
    const float* x    = (const float*)d_in[0];
    const float* geom = (const float*)d_in[1];
    const float* mask = (const float*)d_in[2];
    const float* dx   = (const float*)d_in[3];
    const float* bx   = (const float*)d_in[4];
    float* out = (float*)d_out;

    // 1) zero the interleaved accumulator (41 MB)
    const int n4 = SCRATCH_ELEMS / 4;
    zero_scratch_kernel<<<(n4 + 255) / 256, 256>>>(n4);

    // 2) masked scatter with v4 reductions; persistent half-warps
    bev_scatter_kernel<<<148 * 8, 256>>>(x, geom, mask, dx, bx);

    // 3) interleaved -> planar unpack (covers all of out; no out zero-init)
    bev_unpack_kernel<<<(NGTOT + 255) / 256, 256>>>(out);
}

// round 3
// speedup vs baseline: 1.4703x; 1.1653x over previous
#include <cuda_runtime.h>
#include <cuda_bf16.h>

// Fixed problem shapes
#define BV 4
#define DV 48
#define HV 32
#define WV 88
#define CV 64
#define NXV 200
#define NYV 200
#define HWV (HV * WV)
#define NPRIME (BV * DV * HV * WV)       // 540672 points (divisible by 32)
#define NXY (NXV * NYV)                  // 40000
#define NGROUP (CV / 4)                  // 16 four-channel groups
#define NGTOT (BV * NGROUP * NXY)        // 2,560,000 groups
#define SCRATCH_ELEMS (NGTOT * 4)        // 10,240,000 floats = 41 MB

// Channel-interleaved accumulator: [b][c4][nxy][4] -> 16B-contiguous groups so
// one point's contribution to 4 channels is a single red.global.add.v4.f32.
// Zero-initialized at module load; bev_unpack_kernel re-zeroes it every call,
// so the zero-invariant holds across the correctness run and all graph replays.
__device__ float g_scratch[SCRATCH_ELEMS];

__global__ void bev_scatter_kernel(const float* __restrict__ x,
                                   const float* __restrict__ geom,
                                   const float* __restrict__ mask,
                                   const float* __restrict__ dxp,
                                   const float* __restrict__ bxp) {
    const int lane = threadIdx.x & 31;
    const int warp = (blockIdx.x * blockDim.x + threadIdx.x) >> 5;
    const int nw   = (gridDim.x * blockDim.x) >> 5;

    const float dx0 = dxp[0], dx1 = dxp[1], dx2 = dxp[2];
    const float b0 = bxp[0] - 0.5f * dx0;
    const float b1 = bxp[1] - 0.5f * dx1;
    const float b2 = bxp[2] - 0.5f * dx2;

    const int half = lane >> 4;          // which of the 2 points this iteration
    const int sl   = lane & 15;          // 4-channel group within the point

    for (int p0 = warp * 32; p0 < NPRIME; p0 += nw * 32) {
        // ---- phase 1: all 32 lanes compute one point's voxel base each ----
        const int p = p0 + lane;
        // IEEE fp32 div + truncation toward zero matches reference astype(int32)
        const float gx = (geom[p * 3 + 0] - b0) / dx0;
        const float gy = (geom[p * 3 + 1] - b1) / dx1;
        const float gz = (geom[p * 3 + 2] - b2) / dx2;
        const int ix = (int)gx;
        const int iy = (int)gy;
        const int iz = (int)gz;

        const int hw = p % HWV;
        const int bn = p / (DV * HWV);   // batch index (N=1)

        int base = -1;
        if ((ix >= 0) & (ix < NXV) &
            (iy >= 0) & (iy < NYV) &
            (iz >= 0) & (iz < 1) &
            (mask[(bn * 2 + 1) * HWV + hw] > 0.5f)) {
            base = bn * (NGROUP * NXY) + ix * NYV + iy;
        }

        // ---- phase 2: 16 iterations, 2 points each (lanes 0-15 / 16-31) ----
        #pragma unroll
        for (int j = 0; j < 32; j += 2) {
            const int bj = __shfl_sync(0xffffffffu, base, j + half);
            if (bj >= 0) {
                const float4 v = *reinterpret_cast<const float4*>(
                    x + (size_t)(p0 + j + half) * CV + sl * 4);
                float* dst = g_scratch + (size_t)(bj + sl * NXY) * 4;
                asm volatile(
                    "red.global.add.v4.f32 [%0], {%1, %2, %3, %4};"
                    :: "l"(dst), "f"(v.x), "f"(v.y), "f"(v.z), "f"(v.w)
                    : "memory");
            }
        }
    }
}

// Interleaved scratch -> planar output, then re-zero scratch for the next call.
// Writes EVERY output element, so no separate output zero-init is needed.
__global__ void bev_unpack_kernel(float* __restrict__ out) {
    const int g = blockIdx.x * blockDim.x + threadIdx.x;
    if (g >= NGTOT) return;
    const int nxy = g % NXY;
    const int t   = g / NXY;
    const int c4  = t % NGROUP;
    const int b   = t / NGROUP;

    float4* sp = reinterpret_cast<float4*>(g_scratch) + g;
    const float4 v = *sp;
    *sp = make_float4(0.f, 0.f, 0.f, 0.f);   // restore zero-invariant

    float* o = out + (size_t)(b * CV + c4 * 4) * NXY + nxy;
    o[0 * NXY] = v.x;
    o[1 * NXY] = v.y;
    o[2 * NXY] = v.z;
    o[3 * NXY] = v.w;
}

extern "C" void kernel_launch(void* const* d_in, const int* in_sizes, int n_in,
                              void* d_out, int out_size) {
    const float* x    = (const float*)d_in[0];
    const float* geom = (const float*)d_in[1];
    const float* mask = (const float*)d_in[2];
    const float* dx   = (const float*)d_in[3];
    const float* bx   = (const float*)d_in[4];
    float* out = (float*)d_out;

    // 1) masked scatter with v4 reductions; batched warp-parallel indexing.
    //    1056 blocks x 256 thr = 8448 warps; 16896 batches -> exactly 2 per warp.
    bev_scatter_kernel<<<1056, 256>>>(x, geom, mask, dx, bx);

    // 2) interleaved -> planar unpack + scratch re-zero (covers all of out)
    bev_unpack_kernel<<<(NGTOT + 255) / 256, 256>>>(out);
}

// round 4
// speedup vs baseline: 2.3640x; 1.6079x over previous
#include <cuda_runtime.h>
#include <cuda_bf16.h>

// Fixed problem shapes
#define BV 4
#define DV 48
#define HV 32
#define WV 88
#define CV 64
#define NXV 200
#define NYV 200
#define HWV (HV * WV)
#define NPRIME (BV * DV * HV * WV)       // 540672 points (divisible by 32)
#define NXY (NXV * NYV)                  // 40000
#define NGROUP (CV / 4)                  // 16 four-channel groups
#define NGTOT (BV * NGROUP * NXY)        // 2,560,000 groups
#define SCRATCH_ELEMS (NGTOT * 4)        // 10,240,000 floats = 41 MB

// Channel-interleaved accumulator: [b][c4][nxy][4] -> 16B-contiguous groups so
// one point's contribution to 4 channels is a single red.global.add.v4.f32.
__device__ float g_scratch[SCRATCH_ELEMS];

// One-wave grid-stride zero with 4x float4 ILP per iteration.
__global__ void zero_scratch_kernel() {
    float4* p = reinterpret_cast<float4*>(g_scratch);
    const int n4 = SCRATCH_ELEMS / 4;                 // 2,560,000
    const int stride = gridDim.x * blockDim.x;
    const float4 z = make_float4(0.f, 0.f, 0.f, 0.f);
    for (int i = blockIdx.x * blockDim.x + threadIdx.x; i < n4; i += 4 * stride) {
        p[i] = z;
        if (i + stride     < n4) p[i + stride]     = z;
        if (i + 2 * stride < n4) p[i + 2 * stride] = z;
        if (i + 3 * stride < n4) p[i + 3 * stride] = z;
    }
}

__global__ void bev_scatter_kernel(const float* __restrict__ x,
                                   const float* __restrict__ geom,
                                   const float* __restrict__ mask,
                                   const float* __restrict__ dxp,
                                   const float* __restrict__ bxp) {
    const int lane = threadIdx.x & 31;
    const int warp = (blockIdx.x * blockDim.x + threadIdx.x) >> 5;
    const int nw   = (gridDim.x * blockDim.x) >> 5;

    const float dx0 = dxp[0], dx1 = dxp[1], dx2 = dxp[2];
    const float b0 = bxp[0] - 0.5f * dx0;
    const float b1 = bxp[1] - 0.5f * dx1;
    const float b2 = bxp[2] - 0.5f * dx2;

    const int half = lane >> 4;          // which of the 2 points this iteration
    const int sl   = lane & 15;          // 4-channel group within the point

    for (int p0 = warp * 32; p0 < NPRIME; p0 += nw * 32) {
        // ---- phase 1: all 32 lanes compute one point's voxel base each ----
        const int p = p0 + lane;
        // IEEE fp32 div + truncation toward zero matches reference astype(int32)
        const float gx = (geom[p * 3 + 0] - b0) / dx0;
        const float gy = (geom[p * 3 + 1] - b1) / dx1;
        const float gz = (geom[p * 3 + 2] - b2) / dx2;
        const int ix = (int)gx;
        const int iy = (int)gy;
        const int iz = (int)gz;

        const int hw = p % HWV;
        const int bn = p / (DV * HWV);   // batch index (N=1)

        int base = -1;
        if ((ix >= 0) & (ix < NXV) &
            (iy >= 0) & (iy < NYV) &
            (iz >= 0) & (iz < 1) &
            (mask[(bn * 2 + 1) * HWV + hw] > 0.5f)) {
            base = bn * (NGROUP * NXY) + ix * NYV + iy;
        }

        // ---- phase 2: 16 iterations, 2 points each (lanes 0-15 / 16-31) ----
        #pragma unroll
        for (int j = 0; j < 32; j += 2) {
            const int bj = __shfl_sync(0xffffffffu, base, j + half);
            if (bj >= 0) {
                const float4 v = *reinterpret_cast<const float4*>(
                    x + (size_t)(p0 + j + half) * CV + sl * 4);
                float* dst = g_scratch + (size_t)(bj + sl * NXY) * 4;
                asm volatile(
                    "red.global.add.v4.f32 [%0], {%1, %2, %3, %4};"
                    :: "l"(dst), "f"(v.x), "f"(v.y), "f"(v.z), "f"(v.w)
                    : "memory");
            }
        }
    }
}

// Interleaved scratch -> planar output. No scratch writes here (re-zero is a
// separate kernel). ILP=2: each thread handles two independent groups.
// Output stores use streaming hint so the write-once 41MB doesn't evict the
// L2-resident scratch.
__global__ void bev_unpack_kernel(float* __restrict__ out) {
    const int g0 = blockIdx.x * blockDim.x + threadIdx.x;
    const int HALF = NGTOT / 2;
    if (g0 >= HALF) return;

    #pragma unroll
    for (int k = 0; k < 2; k++) {
        const int g = g0 + k * HALF;
        const int nxy = g % NXY;
        const int t   = g / NXY;
        const int c4  = t % NGROUP;
        const int b   = t / NGROUP;

        const float4 v = *(reinterpret_cast<const float4*>(g_scratch) + g);
        float* o = out + (size_t)(b * CV + c4 * 4) * NXY + nxy;
        __stcs(o + 0 * NXY, v.x);
        __stcs(o + 1 * NXY, v.y);
        __stcs(o + 2 * NXY, v.z);
        __stcs(o + 3 * NXY, v.w);
    }
}

extern "C" void kernel_launch(void* const* d_in, const int* in_sizes, int n_in,
                              void* d_out, int out_size) {
    const float* x    = (const float*)d_in[0];
    const float* geom = (const float*)d_in[1];
    const float* mask = (const float*)d_in[2];
    const float* dx   = (const float*)d_in[3];
    const float* bx   = (const float*)d_in[4];
    float* out = (float*)d_out;

    // 1) zero the interleaved accumulator (41 MB), one-wave grid-stride
    zero_scratch_kernel<<<148 * 8, 256>>>();

    // 2) masked scatter with v4 reductions; batched warp-parallel indexing
    bev_scatter_kernel<<<1056, 256>>>(x, geom, mask, dx, bx);

    // 3) interleaved -> planar unpack (covers every out element)
    bev_unpack_kernel<<<(NGTOT / 2 + 255) / 256, 256>>>(out);
}